// round 1
// baseline (speedup 1.0000x reference)
#include <cuda_runtime.h>
#include <cuda_bf16.h>
#include <math.h>

// Problem constants
#define LNUM 8
#define DDIM 1024
#define HNUM 16
#define DKDIM 64
#define FDIM 4096
#define VDIM 32000
#define SDIM 1024
#define BNUM 2
#define MROWS (BNUM * SDIM)   // 2048

// ---------------- scratch (device globals; no runtime allocation) ----------
__device__ float g_x  [MROWS * DDIM];
__device__ float g_h  [MROWS * DDIM];
__device__ float g_q  [MROWS * DDIM];
__device__ float g_k  [MROWS * DDIM];
__device__ float g_v  [MROWS * DDIM];
__device__ float g_att[MROWS * DDIM];
__device__ float g_mid[MROWS * FDIM];

// ---------------- embedding: x = tok_emb[ids] + pos_emb ---------------------
__global__ void embed_kernel(const int* __restrict__ ids,
                             const float* __restrict__ tok,
                             const float* __restrict__ pos,
                             float* __restrict__ x)
{
    int row = blockIdx.x;              // b*S + s
    int s   = row % SDIM;
    int id  = ids[row];
    int tid = threadIdx.x;
    const float* tr = tok + (size_t)id * DDIM;
    const float* pr = pos + (size_t)s  * DDIM;
    float* xr = x + (size_t)row * DDIM;
    #pragma unroll
    for (int i = 0; i < 4; i++) {
        int c = tid + i * 256;
        xr[c] = tr[c] + pr[c];
    }
}

// ---------------- layernorm: out = (x-mean)*rsqrt(var+eps)*g + b ------------
__global__ void ln_kernel(const float* __restrict__ x,
                          const float* __restrict__ g,
                          const float* __restrict__ b,
                          float* __restrict__ out)
{
    __shared__ float red[256];
    int row = blockIdx.x;
    int tid = threadIdx.x;
    const float* xr = x + (size_t)row * DDIM;

    float vals[4];
    float s = 0.f;
    #pragma unroll
    for (int i = 0; i < 4; i++) { vals[i] = xr[tid + i * 256]; s += vals[i]; }
    red[tid] = s; __syncthreads();
    for (int o = 128; o > 0; o >>= 1) {
        if (tid < o) red[tid] += red[tid + o];
        __syncthreads();
    }
    float mean = red[0] * (1.0f / DDIM);
    __syncthreads();

    float vs = 0.f;
    #pragma unroll
    for (int i = 0; i < 4; i++) { float d = vals[i] - mean; vs += d * d; }
    red[tid] = vs; __syncthreads();
    for (int o = 128; o > 0; o >>= 1) {
        if (tid < o) red[tid] += red[tid + o];
        __syncthreads();
    }
    float inv = rsqrtf(red[0] * (1.0f / DDIM) + 1e-5f);

    float* outr = out + (size_t)row * DDIM;
    #pragma unroll
    for (int i = 0; i < 4; i++) {
        int c = tid + i * 256;
        outr[c] = (vals[i] - mean) * inv * g[c] + b[c];
    }
}

// ---------------- SGEMM: C = A[M,K] @ B[K,N] + bias (opt relu / residual) ---
// BM=BN=128, BK=8, 256 threads, 8x8 per-thread microtile.
template<bool RELU, bool RES>
__global__ void __launch_bounds__(256)
gemm_kernel(const float* __restrict__ A, const float* __restrict__ Bm,
            const float* __restrict__ bias, float* __restrict__ C,
            int M, int N, int K)
{
    const int BK = 8;
    __shared__ float As[BK][128];
    __shared__ float Bs[BK][128];

    int tid = threadIdx.x;
    int bm = blockIdx.y * 128;
    int bn = blockIdx.x * 128;
    int tx = tid & 15;     // col group
    int ty = tid >> 4;     // row group

    int aRow = tid >> 1;
    int aCol = (tid & 1) * 4;
    int bRow = tid >> 5;
    int bCol = (tid & 31) * 4;

    float acc[8][8];
    #pragma unroll
    for (int i = 0; i < 8; i++)
        #pragma unroll
        for (int j = 0; j < 8; j++) acc[i][j] = 0.f;

    const float* Aptr = A + (size_t)(bm + aRow) * K + aCol;
    const float* Bptr = Bm + (size_t)bRow * N + bn + bCol;

    for (int k0 = 0; k0 < K; k0 += BK) {
        float4 av = *(const float4*)(Aptr + k0);
        As[aCol + 0][aRow] = av.x;
        As[aCol + 1][aRow] = av.y;
        As[aCol + 2][aRow] = av.z;
        As[aCol + 3][aRow] = av.w;
        float4 bv = *(const float4*)(Bptr + (size_t)k0 * N);
        *(float4*)(&Bs[bRow][bCol]) = bv;
        __syncthreads();

        #pragma unroll
        for (int kk = 0; kk < BK; kk++) {
            float4 a0 = *(const float4*)&As[kk][ty * 8];
            float4 a1 = *(const float4*)&As[kk][ty * 8 + 4];
            float4 b0 = *(const float4*)&Bs[kk][tx * 8];
            float4 b1 = *(const float4*)&Bs[kk][tx * 8 + 4];
            float ar[8] = {a0.x, a0.y, a0.z, a0.w, a1.x, a1.y, a1.z, a1.w};
            float br[8] = {b0.x, b0.y, b0.z, b0.w, b1.x, b1.y, b1.z, b1.w};
            #pragma unroll
            for (int i = 0; i < 8; i++)
                #pragma unroll
                for (int j = 0; j < 8; j++)
                    acc[i][j] += ar[i] * br[j];
        }
        __syncthreads();
    }

    #pragma unroll
    for (int i = 0; i < 8; i++) {
        int row = bm + ty * 8 + i;
        float* crow = C + (size_t)row * N;
        #pragma unroll
        for (int j = 0; j < 8; j++) {
            int col = bn + tx * 8 + j;
            float vv = acc[i][j] + bias[col];
            if (RELU) vv = fmaxf(vv, 0.f);
            if (RES)  crow[col] += vv;
            else      crow[col]  = vv;
        }
    }
}

// ---------------- causal attention (flash-style, 64x64 tiles) ---------------
// grid: (S/64, H, B), 256 threads, dynamic smem.
#define ATT_SMEM_FLOATS (5 * 64 * 65 + 3 * 64)

__global__ void attn_kernel(const float* __restrict__ q,
                            const float* __restrict__ k,
                            const float* __restrict__ v,
                            float* __restrict__ o)
{
    extern __shared__ float sm[];
    float* Qs  = sm;                 // [64][65]
    float* Ks  = Qs + 64 * 65;
    float* Vs  = Ks + 64 * 65;
    float* Ss  = Vs + 64 * 65;
    float* Os  = Ss + 64 * 65;
    float* mrow = Os + 64 * 65;      // [64]
    float* lrow = mrow + 64;
    float* arow = lrow + 64;

    int qt = blockIdx.x, hh = blockIdx.y, bb = blockIdx.z;
    int tid = threadIdx.x;
    const float scale = 0.125f;      // 1/sqrt(64)

    int r  = tid >> 2;               // 0..63 (I/O mapping)
    int c0 = (tid & 3) * 16;
    int tx = tid & 15;               // compute mapping: 4x4 microtile
    int ty = tid >> 4;

    size_t qbase = ((size_t)(bb * SDIM) + qt * 64) * DDIM + hh * DKDIM;

    #pragma unroll
    for (int i = 0; i < 16; i++) {
        int c = c0 + i;
        Qs[r * 65 + c] = q[qbase + (size_t)r * DDIM + c];
        Os[r * 65 + c] = 0.f;
    }
    if (tid < 64) { mrow[tid] = -1e30f; lrow[tid] = 0.f; }
    __syncthreads();

    for (int kt = 0; kt <= qt; kt++) {
        size_t kbase = ((size_t)(bb * SDIM) + kt * 64) * DDIM + hh * DKDIM;
        #pragma unroll
        for (int i = 0; i < 16; i++) {
            int c = c0 + i;
            Ks[r * 65 + c] = k[kbase + (size_t)r * DDIM + c];
            Vs[r * 65 + c] = v[kbase + (size_t)r * DDIM + c];
        }
        __syncthreads();

        // S = (Q K^T) * scale, causal-masked; 4x4 microtile per thread
        {
            float a4[4][4];
            #pragma unroll
            for (int i = 0; i < 4; i++)
                #pragma unroll
                for (int j = 0; j < 4; j++) a4[i][j] = 0.f;
            for (int d = 0; d < 64; d++) {
                float qa[4], kb[4];
                #pragma unroll
                for (int i = 0; i < 4; i++) qa[i] = Qs[(ty * 4 + i) * 65 + d];
                #pragma unroll
                for (int j = 0; j < 4; j++) kb[j] = Ks[(tx * 4 + j) * 65 + d];
                #pragma unroll
                for (int i = 0; i < 4; i++)
                    #pragma unroll
                    for (int j = 0; j < 4; j++) a4[i][j] += qa[i] * kb[j];
            }
            #pragma unroll
            for (int i = 0; i < 4; i++) {
                int rr = ty * 4 + i;
                #pragma unroll
                for (int j = 0; j < 4; j++) {
                    int cc = tx * 4 + j;
                    float val = a4[i][j] * scale;
                    if (kt == qt && cc > rr) val = -1e30f;
                    Ss[rr * 65 + cc] = val;
                }
            }
        }
        __syncthreads();

        // per-row online softmax state update (64 threads)
        if (tid < 64) {
            int rr = tid;
            float tm = -1e30f;
            for (int c = 0; c < 64; c++) tm = fmaxf(tm, Ss[rr * 65 + c]);
            float mold = mrow[rr];
            float mnew = fmaxf(mold, tm);
            float al = expf(mold - mnew);
            float sum = 0.f;
            for (int c = 0; c < 64; c++) {
                float p = expf(Ss[rr * 65 + c] - mnew);
                Ss[rr * 65 + c] = p;
                sum += p;
            }
            lrow[rr] = lrow[rr] * al + sum;
            mrow[rr] = mnew;
            arow[rr] = al;
        }
        __syncthreads();

        // O = O*alpha + P @ V ; 4x4 microtile per thread
        {
            float oacc[4][4];
            #pragma unroll
            for (int i = 0; i < 4; i++) {
                float al = arow[ty * 4 + i];
                #pragma unroll
                for (int j = 0; j < 4; j++)
                    oacc[i][j] = Os[(ty * 4 + i) * 65 + tx * 4 + j] * al;
            }
            for (int jj = 0; jj < 64; jj++) {
                float pa[4], vb[4];
                #pragma unroll
                for (int i = 0; i < 4; i++) pa[i] = Ss[(ty * 4 + i) * 65 + jj];
                #pragma unroll
                for (int j = 0; j < 4; j++) vb[j] = Vs[jj * 65 + tx * 4 + j];
                #pragma unroll
                for (int i = 0; i < 4; i++)
                    #pragma unroll
                    for (int j = 0; j < 4; j++) oacc[i][j] += pa[i] * vb[j];
            }
            #pragma unroll
            for (int i = 0; i < 4; i++)
                #pragma unroll
                for (int j = 0; j < 4; j++)
                    Os[(ty * 4 + i) * 65 + tx * 4 + j] = oacc[i][j];
        }
        __syncthreads();
    }

    float invl = 1.f / lrow[r];
    #pragma unroll
    for (int i = 0; i < 16; i++) {
        int c = c0 + i;
        o[qbase + (size_t)r * DDIM + c] = Os[r * 65 + c] * invl;
    }
}

// ---------------- host orchestration ----------------------------------------
extern "C" void kernel_launch(void* const* d_in, const int* in_sizes, int n_in,
                              void* d_out, int out_size)
{
    const int*   ids   = (const int*)  d_in[0];
    const float* tok   = (const float*)d_in[1];
    const float* pos   = (const float*)d_in[2];
    const float* Wq    = (const float*)d_in[3];
    const float* bq    = (const float*)d_in[4];
    const float* Wk    = (const float*)d_in[5];
    const float* bk    = (const float*)d_in[6];
    const float* Wv    = (const float*)d_in[7];
    const float* bv    = (const float*)d_in[8];
    const float* Wo    = (const float*)d_in[9];
    const float* bo    = (const float*)d_in[10];
    const float* W1    = (const float*)d_in[11];
    const float* b1    = (const float*)d_in[12];
    const float* W2    = (const float*)d_in[13];
    const float* b2    = (const float*)d_in[14];
    const float* ln1g  = (const float*)d_in[15];
    const float* ln1b  = (const float*)d_in[16];
    const float* ln2g  = (const float*)d_in[17];
    const float* ln2b  = (const float*)d_in[18];
    const float* lnfg  = (const float*)d_in[19];
    const float* lnfb  = (const float*)d_in[20];
    const float* Wout  = (const float*)d_in[21];
    const float* bout  = (const float*)d_in[22];
    float* out = (float*)d_out;

    float *x, *h, *q, *k, *v, *att, *mid;
    cudaGetSymbolAddress((void**)&x,   g_x);
    cudaGetSymbolAddress((void**)&h,   g_h);
    cudaGetSymbolAddress((void**)&q,   g_q);
    cudaGetSymbolAddress((void**)&k,   g_k);
    cudaGetSymbolAddress((void**)&v,   g_v);
    cudaGetSymbolAddress((void**)&att, g_att);
    cudaGetSymbolAddress((void**)&mid, g_mid);

    const int attSmem = ATT_SMEM_FLOATS * (int)sizeof(float);
    cudaFuncSetAttribute(attn_kernel, cudaFuncAttributeMaxDynamicSharedMemorySize, attSmem);

    embed_kernel<<<MROWS, 256>>>(ids, tok, pos, x);

    dim3 gD (DDIM / 128, MROWS / 128);   // N=1024
    dim3 gF (FDIM / 128, MROWS / 128);   // N=4096
    dim3 gV (VDIM / 128, MROWS / 128);   // N=32000
    dim3 gAtt(SDIM / 64, HNUM, BNUM);

    for (int l = 0; l < LNUM; l++) {
        size_t wDD = (size_t)l * DDIM * DDIM;
        size_t wDF = (size_t)l * DDIM * FDIM;

        ln_kernel<<<MROWS, 256>>>(x, ln1g + l * DDIM, ln1b + l * DDIM, h);

        gemm_kernel<false, false><<<gD, 256>>>(h, Wq + wDD, bq + l * DDIM, q, MROWS, DDIM, DDIM);
        gemm_kernel<false, false><<<gD, 256>>>(h, Wk + wDD, bk + l * DDIM, k, MROWS, DDIM, DDIM);
        gemm_kernel<false, false><<<gD, 256>>>(h, Wv + wDD, bv + l * DDIM, v, MROWS, DDIM, DDIM);

        attn_kernel<<<gAtt, 256, attSmem>>>(q, k, v, att);

        gemm_kernel<false, true><<<gD, 256>>>(att, Wo + wDD, bo + l * DDIM, x, MROWS, DDIM, DDIM);

        ln_kernel<<<MROWS, 256>>>(x, ln2g + l * DDIM, ln2b + l * DDIM, h);

        gemm_kernel<true,  false><<<gF, 256>>>(h,   W1 + wDF, b1 + l * FDIM, mid, MROWS, FDIM, DDIM);
        gemm_kernel<false, true ><<<gD, 256>>>(mid, W2 + wDF, b2 + l * DDIM, x,   MROWS, DDIM, FDIM);
    }

    ln_kernel<<<MROWS, 256>>>(x, lnfg, lnfb, h);
    gemm_kernel<false, false><<<gV, 256>>>(h, Wout, bout, out, MROWS, VDIM, DDIM);
}

// round 3
// speedup vs baseline: 3.5278x; 3.5278x over previous
#include <cuda_runtime.h>
#include <cuda_bf16.h>
#include <math.h>
#include <stdint.h>

// Problem constants
#define LNUM 8
#define DDIM 1024
#define HNUM 16
#define DKDIM 64
#define FDIM 4096
#define VDIM 32000
#define SDIM 1024
#define BNUM 2
#define MROWS (BNUM * SDIM)   // 2048

// ---------------- scratch (device globals; no runtime allocation) ----------
__device__ float g_x  [MROWS * DDIM];
__device__ float g_h  [MROWS * DDIM];
__device__ float g_q  [MROWS * DDIM];
__device__ float g_k  [MROWS * DDIM];
__device__ float g_v  [MROWS * DDIM];
__device__ float g_att[MROWS * DDIM];
__device__ float g_mid[MROWS * FDIM];

// ======================= PTX helpers (portable, sm_80+) =====================
__device__ __forceinline__ uint32_t smem_u32(const void* p) {
    uint32_t a;
    asm("{ .reg .u64 t; cvta.to.shared.u64 t, %1; cvt.u32.u64 %0, t; }"
        : "=r"(a) : "l"(p));
    return a;
}

__device__ __forceinline__ void ldsm4(uint32_t* r, uint32_t addr) {
    asm volatile("ldmatrix.sync.aligned.m8n8.x4.shared.b16 {%0,%1,%2,%3}, [%4];"
        : "=r"(r[0]), "=r"(r[1]), "=r"(r[2]), "=r"(r[3]) : "r"(addr));
}
__device__ __forceinline__ void ldsm4t(uint32_t* r, uint32_t addr) {
    asm volatile("ldmatrix.sync.aligned.m8n8.x4.trans.shared.b16 {%0,%1,%2,%3}, [%4];"
        : "=r"(r[0]), "=r"(r[1]), "=r"(r[2]), "=r"(r[3]) : "r"(addr));
}
__device__ __forceinline__ void mma16816(float* c, const uint32_t* a,
                                         const uint32_t* b) {
    asm volatile(
        "mma.sync.aligned.m16n8k16.row.col.f32.bf16.bf16.f32 "
        "{%0,%1,%2,%3}, {%4,%5,%6,%7}, {%8,%9}, {%0,%1,%2,%3};"
        : "+f"(c[0]), "+f"(c[1]), "+f"(c[2]), "+f"(c[3])
        : "r"(a[0]), "r"(a[1]), "r"(a[2]), "r"(a[3]), "r"(b[0]), "r"(b[1]));
}

__device__ __forceinline__ uint32_t packbf2(__nv_bfloat16 a, __nv_bfloat16 b) {
    __nv_bfloat162 t;
    t.x = a; t.y = b;
    return *reinterpret_cast<uint32_t*>(&t);
}

// split fp32x4 -> bf16 hi pair-words + bf16 lo pair-words
__device__ __forceinline__ void cvt_split4(float4 v, uint32_t& h01, uint32_t& h23,
                                           uint32_t& l01, uint32_t& l23) {
    __nv_bfloat16 hx = __float2bfloat16(v.x);
    __nv_bfloat16 hy = __float2bfloat16(v.y);
    __nv_bfloat16 hz = __float2bfloat16(v.z);
    __nv_bfloat16 hw = __float2bfloat16(v.w);
    float rx = v.x - __bfloat162float(hx);
    float ry = v.y - __bfloat162float(hy);
    float rz = v.z - __bfloat162float(hz);
    float rw = v.w - __bfloat162float(hw);
    h01 = packbf2(hx, hy);
    h23 = packbf2(hz, hw);
    l01 = packbf2(__float2bfloat16(rx), __float2bfloat16(ry));
    l23 = packbf2(__float2bfloat16(rz), __float2bfloat16(rw));
}

// ---------------- tensor-core (mma.sync) GEMM -------------------------------
// C[M,N] = A[M,K] @ B[K,N] (+bias, opt relu/residual), split-precision bf16.
// CTA tile 128x128x32, 8 warps (2x4), warp tile 64x32, m16n8k16 mma.
#define BM 128
#define BN 128
#define BK 32
#define ASTR 56                 // bf16 elems per A smem row (pad from 32)
#define BSTR 136                // bf16 elems per B smem row (pad from 128)
#define A_SZ (BM * ASTR)        // 7168 elems per buffer per precision
#define B_SZ (BK * BSTR)        // 4352
// byte offsets within dynamic smem
#define AHI_B 0
#define ALO_B (AHI_B + 2 * A_SZ * 2)   // 28672
#define BHI_B (ALO_B + 2 * A_SZ * 2)   // 57344
#define BLO_B (BHI_B + 2 * B_SZ * 2)   // 74752
#define SMEM_MM (BLO_B + 2 * B_SZ * 2) // 92160 bytes

template<bool RELU, bool RES>
__global__ void __launch_bounds__(256, 1)
gemm_mma(const float* __restrict__ A, const float* __restrict__ Bm,
         const float* __restrict__ bias, float* __restrict__ C,
         int M, int N, int K)
{
    extern __shared__ char smem[];
    uint32_t sb = smem_u32(smem);

    int tid  = threadIdx.x;
    int wid  = tid >> 5;
    int lane = tid & 31;
    int bn = blockIdx.x * BN;
    int bm = blockIdx.y * BM;
    int wm = (wid >> 2) * 64;    // warp row offset in tile (0 / 64)
    int wn = (wid & 3) * 32;     // warp col offset in tile (0/32/64/96)

    // ---- gmem load mapping (per thread) ----
    int ar = tid >> 1;                 // A row 0..127
    int ac = (tid & 1) * 16;           // A col base (16 floats)
    int br = tid >> 3;                 // B k-row 0..31
    int bc = (tid & 7) * 16;           // B col base (16 floats)
    const float* Ap = A + (size_t)(bm + ar) * K + ac;
    const float* Bp = Bm + (size_t)br * N + bn + bc;

    float acc[4][4][4];
    #pragma unroll
    for (int i = 0; i < 4; i++)
        #pragma unroll
        for (int j = 0; j < 4; j++)
            #pragma unroll
            for (int r = 0; r < 4; r++) acc[i][j][r] = 0.f;

    float4 aR[4], bR[4];

    // ---- helpers as macros over locals ----
#define LOADG(s)                                                             \
    {                                                                        \
        const float* ap_ = Ap + (s) * BK;                                    \
        _Pragma("unroll")                                                    \
        for (int i = 0; i < 4; i++) aR[i] = *(const float4*)(ap_ + 4 * i);   \
        const float* bp_ = Bp + (size_t)(s) * BK * N;                        \
        _Pragma("unroll")                                                    \
        for (int i = 0; i < 4; i++) bR[i] = *(const float4*)(bp_ + 4 * i);   \
    }

#define STOREST(buf)                                                          \
    {                                                                         \
        _Pragma("unroll")                                                     \
        for (int i = 0; i < 4; i++) {                                         \
            uint32_t h01, h23, l01, l23;                                      \
            cvt_split4(aR[i], h01, h23, l01, l23);                            \
            uint32_t eo = ((buf) * A_SZ + ar * ASTR + ac + 4 * i) * 2;        \
            *(uint2*)(smem + AHI_B + eo) = make_uint2(h01, h23);              \
            *(uint2*)(smem + ALO_B + eo) = make_uint2(l01, l23);              \
        }                                                                     \
        _Pragma("unroll")                                                     \
        for (int i = 0; i < 4; i++) {                                         \
            uint32_t h01, h23, l01, l23;                                      \
            cvt_split4(bR[i], h01, h23, l01, l23);                            \
            uint32_t eo = ((buf) * B_SZ + br * BSTR + bc + 4 * i) * 2;        \
            *(uint2*)(smem + BHI_B + eo) = make_uint2(h01, h23);              \
            *(uint2*)(smem + BLO_B + eo) = make_uint2(l01, l23);              \
        }                                                                     \
    }

    LOADG(0);
    STOREST(0);
    __syncthreads();

    const int nst = K / BK;
    for (int s = 0; s < nst; s++) {
        int buf = s & 1;
        bool more = (s + 1) < nst;
        if (more) LOADG(s + 1);

        #pragma unroll
        for (int kk = 0; kk < 2; kk++) {
            uint32_t ah[4][4], al[4][4], bh[2][4], bl[2][4];
            int arow = wm + (lane & 15);
            int kcol = kk * 16 + (lane >> 4) * 8;
            #pragma unroll
            for (int mt = 0; mt < 4; mt++) {
                uint32_t eo = (uint32_t)(buf * A_SZ + (arow + mt * 16) * ASTR + kcol) * 2;
                ldsm4(ah[mt], sb + AHI_B + eo);
                ldsm4(al[mt], sb + ALO_B + eo);
            }
            int krow = kk * 16 + (lane & 15);
            int ncol = wn + (lane >> 4) * 8;
            #pragma unroll
            for (int nt2 = 0; nt2 < 2; nt2++) {
                uint32_t eo = (uint32_t)(buf * B_SZ + krow * BSTR + ncol + nt2 * 16) * 2;
                ldsm4t(bh[nt2], sb + BHI_B + eo);
                ldsm4t(bl[nt2], sb + BLO_B + eo);
            }
            #pragma unroll
            for (int mt = 0; mt < 4; mt++)
                #pragma unroll
                for (int nt = 0; nt < 4; nt++) {
                    const uint32_t* bhp = &bh[nt >> 1][(nt & 1) * 2];
                    const uint32_t* blp = &bl[nt >> 1][(nt & 1) * 2];
                    mma16816(acc[mt][nt], ah[mt], bhp);
                    mma16816(acc[mt][nt], ah[mt], blp);
                    mma16816(acc[mt][nt], al[mt], bhp);
                }
        }

        if (more) STOREST(buf ^ 1);
        __syncthreads();
    }

    // ---- epilogue: write accumulators directly to gmem ----
    #pragma unroll
    for (int mt = 0; mt < 4; mt++) {
        int grow = bm + wm + mt * 16 + (lane >> 2);
        float* c0 = C + (size_t)grow * N;
        float* c1 = C + (size_t)(grow + 8) * N;
        #pragma unroll
        for (int nt = 0; nt < 4; nt++) {
            int gcol = bn + wn + nt * 8 + (lane & 3) * 2;
            float2 bb = *(const float2*)(bias + gcol);
            float v0 = acc[mt][nt][0] + bb.x;
            float v1 = acc[mt][nt][1] + bb.y;
            float v2 = acc[mt][nt][2] + bb.x;
            float v3 = acc[mt][nt][3] + bb.y;
            if (RELU) {
                v0 = fmaxf(v0, 0.f); v1 = fmaxf(v1, 0.f);
                v2 = fmaxf(v2, 0.f); v3 = fmaxf(v3, 0.f);
            }
            if (RES) {
                float2 o0 = *(const float2*)(c0 + gcol);
                float2 o1 = *(const float2*)(c1 + gcol);
                v0 += o0.x; v1 += o0.y; v2 += o1.x; v3 += o1.y;
            }
            *(float2*)(c0 + gcol) = make_float2(v0, v1);
            *(float2*)(c1 + gcol) = make_float2(v2, v3);
        }
    }
#undef LOADG
#undef STOREST
}

// ---------------- embedding -------------------------------------------------
__global__ void embed_kernel(const int* __restrict__ ids,
                             const float* __restrict__ tok,
                             const float* __restrict__ pos,
                             float* __restrict__ x)
{
    int row = blockIdx.x;
    int s   = row % SDIM;
    int id  = ids[row];
    int tid = threadIdx.x;
    const float* tr = tok + (size_t)id * DDIM;
    const float* pr = pos + (size_t)s  * DDIM;
    float* xr = x + (size_t)row * DDIM;
    #pragma unroll
    for (int i = 0; i < 4; i++) {
        int c = tid + i * 256;
        xr[c] = tr[c] + pr[c];
    }
}

// ---------------- layernorm --------------------------------------------------
__global__ void ln_kernel(const float* __restrict__ x,
                          const float* __restrict__ g,
                          const float* __restrict__ b,
                          float* __restrict__ out)
{
    __shared__ float red[256];
    int row = blockIdx.x;
    int tid = threadIdx.x;
    const float* xr = x + (size_t)row * DDIM;

    float vals[4];
    float s = 0.f;
    #pragma unroll
    for (int i = 0; i < 4; i++) { vals[i] = xr[tid + i * 256]; s += vals[i]; }
    red[tid] = s; __syncthreads();
    for (int o = 128; o > 0; o >>= 1) {
        if (tid < o) red[tid] += red[tid + o];
        __syncthreads();
    }
    float mean = red[0] * (1.0f / DDIM);
    __syncthreads();

    float vs = 0.f;
    #pragma unroll
    for (int i = 0; i < 4; i++) { float d = vals[i] - mean; vs += d * d; }
    red[tid] = vs; __syncthreads();
    for (int o = 128; o > 0; o >>= 1) {
        if (tid < o) red[tid] += red[tid + o];
        __syncthreads();
    }
    float inv = rsqrtf(red[0] * (1.0f / DDIM) + 1e-5f);

    float* outr = out + (size_t)row * DDIM;
    #pragma unroll
    for (int i = 0; i < 4; i++) {
        int c = tid + i * 256;
        outr[c] = (vals[i] - mean) * inv * g[c] + b[c];
    }
}

// ---------------- causal attention (flash-style, 64x64 tiles) ---------------
#define ATT_SMEM_FLOATS (5 * 64 * 65 + 3 * 64)

__global__ void attn_kernel(const float* __restrict__ q,
                            const float* __restrict__ k,
                            const float* __restrict__ v,
                            float* __restrict__ o)
{
    extern __shared__ float sm[];
    float* Qs  = sm;
    float* Ks  = Qs + 64 * 65;
    float* Vs  = Ks + 64 * 65;
    float* Ss  = Vs + 64 * 65;
    float* Os  = Ss + 64 * 65;
    float* mrow = Os + 64 * 65;
    float* lrow = mrow + 64;
    float* arow = lrow + 64;

    int qt = blockIdx.x, hh = blockIdx.y, bb = blockIdx.z;
    int tid = threadIdx.x;
    const float scale = 0.125f;

    int r  = tid >> 2;
    int c0 = (tid & 3) * 16;
    int tx = tid & 15;
    int ty = tid >> 4;

    size_t qbase = ((size_t)(bb * SDIM) + qt * 64) * DDIM + hh * DKDIM;

    #pragma unroll
    for (int i = 0; i < 16; i++) {
        int c = c0 + i;
        Qs[r * 65 + c] = q[qbase + (size_t)r * DDIM + c];
        Os[r * 65 + c] = 0.f;
    }
    if (tid < 64) { mrow[tid] = -1e30f; lrow[tid] = 0.f; }
    __syncthreads();

    for (int kt = 0; kt <= qt; kt++) {
        size_t kbase = ((size_t)(bb * SDIM) + kt * 64) * DDIM + hh * DKDIM;
        #pragma unroll
        for (int i = 0; i < 16; i++) {
            int c = c0 + i;
            Ks[r * 65 + c] = k[kbase + (size_t)r * DDIM + c];
            Vs[r * 65 + c] = v[kbase + (size_t)r * DDIM + c];
        }
        __syncthreads();

        {
            float a4[4][4];
            #pragma unroll
            for (int i = 0; i < 4; i++)
                #pragma unroll
                for (int j = 0; j < 4; j++) a4[i][j] = 0.f;
            for (int d = 0; d < 64; d++) {
                float qa[4], kb[4];
                #pragma unroll
                for (int i = 0; i < 4; i++) qa[i] = Qs[(ty * 4 + i) * 65 + d];
                #pragma unroll
                for (int j = 0; j < 4; j++) kb[j] = Ks[(tx * 4 + j) * 65 + d];
                #pragma unroll
                for (int i = 0; i < 4; i++)
                    #pragma unroll
                    for (int j = 0; j < 4; j++) a4[i][j] += qa[i] * kb[j];
            }
            #pragma unroll
            for (int i = 0; i < 4; i++) {
                int rr = ty * 4 + i;
                #pragma unroll
                for (int j = 0; j < 4; j++) {
                    int cc = tx * 4 + j;
                    float val = a4[i][j] * scale;
                    if (kt == qt && cc > rr) val = -1e30f;
                    Ss[rr * 65 + cc] = val;
                }
            }
        }
        __syncthreads();

        if (tid < 64) {
            int rr = tid;
            float tm = -1e30f;
            for (int c = 0; c < 64; c++) tm = fmaxf(tm, Ss[rr * 65 + c]);
            float mold = mrow[rr];
            float mnew = fmaxf(mold, tm);
            float al = expf(mold - mnew);
            float sum = 0.f;
            for (int c = 0; c < 64; c++) {
                float p = expf(Ss[rr * 65 + c] - mnew);
                Ss[rr * 65 + c] = p;
                sum += p;
            }
            lrow[rr] = lrow[rr] * al + sum;
            mrow[rr] = mnew;
            arow[rr] = al;
        }
        __syncthreads();

        {
            float oacc[4][4];
            #pragma unroll
            for (int i = 0; i < 4; i++) {
                float al = arow[ty * 4 + i];
                #pragma unroll
                for (int j = 0; j < 4; j++)
                    oacc[i][j] = Os[(ty * 4 + i) * 65 + tx * 4 + j] * al;
            }
            for (int jj = 0; jj < 64; jj++) {
                float pa[4], vb[4];
                #pragma unroll
                for (int i = 0; i < 4; i++) pa[i] = Ss[(ty * 4 + i) * 65 + jj];
                #pragma unroll
                for (int j = 0; j < 4; j++) vb[j] = Vs[jj * 65 + tx * 4 + j];
                #pragma unroll
                for (int i = 0; i < 4; i++)
                    #pragma unroll
                    for (int j = 0; j < 4; j++) oacc[i][j] += pa[i] * vb[j];
            }
            #pragma unroll
            for (int i = 0; i < 4; i++)
                #pragma unroll
                for (int j = 0; j < 4; j++)
                    Os[(ty * 4 + i) * 65 + tx * 4 + j] = oacc[i][j];
        }
        __syncthreads();
    }

    float invl = 1.f / lrow[r];
    #pragma unroll
    for (int i = 0; i < 16; i++) {
        int c = c0 + i;
        o[qbase + (size_t)r * DDIM + c] = Os[r * 65 + c] * invl;
    }
}

// ---------------- host orchestration ----------------------------------------
extern "C" void kernel_launch(void* const* d_in, const int* in_sizes, int n_in,
                              void* d_out, int out_size)
{
    const int*   ids   = (const int*)  d_in[0];
    const float* tok   = (const float*)d_in[1];
    const float* pos   = (const float*)d_in[2];
    const float* Wq    = (const float*)d_in[3];
    const float* bq    = (const float*)d_in[4];
    const float* Wk    = (const float*)d_in[5];
    const float* bk    = (const float*)d_in[6];
    const float* Wv    = (const float*)d_in[7];
    const float* bv    = (const float*)d_in[8];
    const float* Wo    = (const float*)d_in[9];
    const float* bo    = (const float*)d_in[10];
    const float* W1    = (const float*)d_in[11];
    const float* b1    = (const float*)d_in[12];
    const float* W2    = (const float*)d_in[13];
    const float* b2    = (const float*)d_in[14];
    const float* ln1g  = (const float*)d_in[15];
    const float* ln1b  = (const float*)d_in[16];
    const float* ln2g  = (const float*)d_in[17];
    const float* ln2b  = (const float*)d_in[18];
    const float* lnfg  = (const float*)d_in[19];
    const float* lnfb  = (const float*)d_in[20];
    const float* Wout  = (const float*)d_in[21];
    const float* bout  = (const float*)d_in[22];
    float* out = (float*)d_out;

    float *x, *h, *q, *k, *v, *att, *mid;
    cudaGetSymbolAddress((void**)&x,   g_x);
    cudaGetSymbolAddress((void**)&h,   g_h);
    cudaGetSymbolAddress((void**)&q,   g_q);
    cudaGetSymbolAddress((void**)&k,   g_k);
    cudaGetSymbolAddress((void**)&v,   g_v);
    cudaGetSymbolAddress((void**)&att, g_att);
    cudaGetSymbolAddress((void**)&mid, g_mid);

    const int attSmem = ATT_SMEM_FLOATS * (int)sizeof(float);
    cudaFuncSetAttribute(attn_kernel, cudaFuncAttributeMaxDynamicSharedMemorySize, attSmem);
    cudaFuncSetAttribute(gemm_mma<false, false>, cudaFuncAttributeMaxDynamicSharedMemorySize, SMEM_MM);
    cudaFuncSetAttribute(gemm_mma<true,  false>, cudaFuncAttributeMaxDynamicSharedMemorySize, SMEM_MM);
    cudaFuncSetAttribute(gemm_mma<false, true >, cudaFuncAttributeMaxDynamicSharedMemorySize, SMEM_MM);

    embed_kernel<<<MROWS, 256>>>(ids, tok, pos, x);

    dim3 gD (DDIM / BN, MROWS / BM);   // 8  x 16
    dim3 gF (FDIM / BN, MROWS / BM);   // 32 x 16
    dim3 gV (VDIM / BN, MROWS / BM);   // 250 x 16
    dim3 gAtt(SDIM / 64, HNUM, BNUM);

    for (int l = 0; l < LNUM; l++) {
        size_t wDD = (size_t)l * DDIM * DDIM;
        size_t wDF = (size_t)l * DDIM * FDIM;

        ln_kernel<<<MROWS, 256>>>(x, ln1g + l * DDIM, ln1b + l * DDIM, h);

        gemm_mma<false, false><<<gD, 256, SMEM_MM>>>(h, Wq + wDD, bq + l * DDIM, q, MROWS, DDIM, DDIM);
        gemm_mma<false, false><<<gD, 256, SMEM_MM>>>(h, Wk + wDD, bk + l * DDIM, k, MROWS, DDIM, DDIM);
        gemm_mma<false, false><<<gD, 256, SMEM_MM>>>(h, Wv + wDD, bv + l * DDIM, v, MROWS, DDIM, DDIM);

        attn_kernel<<<gAtt, 256, attSmem>>>(q, k, v, att);

        gemm_mma<false, true><<<gD, 256, SMEM_MM>>>(att, Wo + wDD, bo + l * DDIM, x, MROWS, DDIM, DDIM);

        ln_kernel<<<MROWS, 256>>>(x, ln2g + l * DDIM, ln2b + l * DDIM, h);

        gemm_mma<true,  false><<<gF, 256, SMEM_MM>>>(h,   W1 + wDF, b1 + l * FDIM, mid, MROWS, FDIM, DDIM);
        gemm_mma<false, true ><<<gD, 256, SMEM_MM>>>(mid, W2 + wDF, b2 + l * DDIM, x,   MROWS, DDIM, FDIM);
    }

    ln_kernel<<<MROWS, 256>>>(x, lnfg, lnfb, h);
    gemm_mma<false, false><<<gV, 256, SMEM_MM>>>(h, Wout, bout, out, MROWS, VDIM, DDIM);
}